// round 1
// baseline (speedup 1.0000x reference)
#include <cuda_runtime.h>

#define B_   2
#define C_   128
#define H_   96
#define W_   96
#define HW_  9216     // 96*96
#define NPIX 18432    // B*H*W

// Scratch for q and k (allocation-free rule: __device__ globals)
__device__ __align__(16) float g_q[B_ * C_ * HW_];
__device__ __align__(16) float g_k[B_ * C_ * HW_];

// ---------------------------------------------------------------------------
// Kernel 1: q = Wq @ x, k = Wk @ x   (1x1 convs as GEMM over pixels)
// Block: 32 pixels x all 128 out-channels, both matrices.
// Threads 256: thread = (4 co) x (4 px), 32 accumulators.
// ---------------------------------------------------------------------------
__global__ __launch_bounds__(256) void qk_gemm_kernel(
    const float* __restrict__ x,
    const float* __restrict__ wq,
    const float* __restrict__ wk)
{
    __shared__ float sq[128 * 33];   // wq tile [co][ci_local], padded stride 33
    __shared__ float sk[128 * 33];
    __shared__ __align__(16) float sx[32 * 36];    // x tile [ci_local][px], padded stride 36

    const int tid = threadIdx.x;
    const int cg  = tid >> 3;          // 0..31
    const int pg  = tid & 7;           // 0..7
    const int co0 = cg * 4;
    const int px0 = pg * 4;

    const int pix0 = blockIdx.x * 32;  // 32-pixel blocks never cross batch (9216 % 32 == 0)
    const int b    = pix0 / HW_;
    const int off0 = pix0 - b * HW_;

    float aq[4][4] = {};
    float ak[4][4] = {};

    for (int kt = 0; kt < 4; kt++) {
        // Load weight tiles (coalesced global, conflict-free smem)
        for (int i = tid; i < 4096; i += 256) {
            int co  = i >> 5;
            int cil = i & 31;
            int gci = kt * 32 + cil;
            sq[co * 33 + cil] = wq[co * 128 + gci];
            sk[co * 33 + cil] = wk[co * 128 + gci];
        }
        // Load x tile [ci_local][px]
        for (int i = tid; i < 1024; i += 256) {
            int cil = i >> 5;
            int px  = i & 31;
            sx[cil * 36 + px] = x[(size_t)(b * C_ + kt * 32 + cil) * HW_ + off0 + px];
        }
        __syncthreads();

        #pragma unroll
        for (int kk = 0; kk < 32; kk++) {
            float4 xv = *(const float4*)&sx[kk * 36 + px0];
            float xr[4] = {xv.x, xv.y, xv.z, xv.w};
            #pragma unroll
            for (int i = 0; i < 4; i++) {
                float wqv = sq[(co0 + i) * 33 + kk];
                float wkv = sk[(co0 + i) * 33 + kk];
                #pragma unroll
                for (int j = 0; j < 4; j++) {
                    aq[i][j] = fmaf(wqv, xr[j], aq[i][j]);
                    ak[i][j] = fmaf(wkv, xr[j], ak[i][j]);
                }
            }
        }
        __syncthreads();
    }

    #pragma unroll
    for (int i = 0; i < 4; i++) {
        size_t o = (size_t)(b * C_ + co0 + i) * HW_ + off0 + px0;
        *(float4*)&g_q[o] = make_float4(aq[i][0], aq[i][1], aq[i][2], aq[i][3]);
        *(float4*)&g_k[o] = make_float4(ak[i][0], ak[i][1], ak[i][2], ak[i][3]);
    }
}

// ---------------------------------------------------------------------------
// Kernel 2: per-channel 7x7 window softmax attention.
// Block = (b, c, 16x32 pixel tile). 128 threads, each owns a 4-pixel strip.
// k/v tile (with 3-halo, zero-filled OOB) staged in smem; rows read as float4.
// l = q*(k + rel); rel_h[c][kh] for c<64, rel_w[c-64][kw] for c>=64.
// exp via single MUFU (fold log2e into q).
// ---------------------------------------------------------------------------
#define TH 16
#define TW 32
#define HALO_R (TH + 6)   // 22
#define HALO_C (TW + 6)   // 38
#define SROW   40         // padded smem row stride (160B, 16B multiple)

__global__ __launch_bounds__(128) void attn_kernel(
    const float* __restrict__ v_g,
    const float* __restrict__ rel_h,
    const float* __restrict__ rel_w,
    float* __restrict__ out)
{
    __shared__ __align__(16) float skm[HALO_R * SROW];
    __shared__ __align__(16) float svm[HALO_R * SROW];

    const int tid  = threadIdx.x;
    const int c    = blockIdx.y;
    const int b    = blockIdx.z;
    const int tile = blockIdx.x;          // 0..17
    const int tx   = tile % 3;
    const int ty   = tile / 3;
    const int w0   = tx * TW;
    const int h0   = ty * TH;

    const size_t imgoff = (size_t)(b * C_ + c) * HW_;
    const float* kimg = g_k + imgoff;
    const float* vimg = v_g + imgoff;

    // Stage haloed k/v tile (zero-fill out-of-bounds -> matches pad-then-unfold+rel)
    for (int i = tid; i < HALO_R * HALO_C; i += 128) {
        int rr  = i / HALO_C;
        int col = i - rr * HALO_C;
        int gr  = h0 - 3 + rr;
        int gc  = w0 - 3 + col;
        bool inb = ((unsigned)gr < 96u) && ((unsigned)gc < 96u);
        float kv = 0.f, vv = 0.f;
        if (inb) {
            kv = kimg[gr * 96 + gc];
            vv = vimg[gr * 96 + gc];
        }
        skm[rr * SROW + col] = kv;
        svm[rr * SROW + col] = vv;
    }
    __syncthreads();

    const int r  = tid >> 3;            // 0..15 row within tile
    const int x0 = (tid & 7) * 4;       // strip start col within tile

    const float L2E = 1.4426950408889634f;
    float4 qv = *(const float4*)&g_q[imgoff + (size_t)(h0 + r) * 96 + w0 + x0];
    float qe[4] = {qv.x * L2E, qv.y * L2E, qv.z * L2E, qv.w * L2E};

    float s[4] = {0.f, 0.f, 0.f, 0.f};
    float a[4] = {0.f, 0.f, 0.f, 0.f};

    if (c < 64) {
        // rel depends on kh only
        float rh[7];
        #pragma unroll
        for (int j = 0; j < 7; j++) rh[j] = rel_h[c * 7 + j];

        #pragma unroll
        for (int kh = 0; kh < 7; kh++) {
            int base = (r + kh) * SROW + x0;
            float4 k0 = *(const float4*)&skm[base];
            float4 k1 = *(const float4*)&skm[base + 4];
            float4 k2 = *(const float4*)&skm[base + 8];
            float4 v0 = *(const float4*)&svm[base];
            float4 v1 = *(const float4*)&svm[base + 4];
            float4 v2 = *(const float4*)&svm[base + 8];
            float kf[10] = {k0.x,k0.y,k0.z,k0.w,k1.x,k1.y,k1.z,k1.w,k2.x,k2.y};
            float vf[10] = {v0.x,v0.y,v0.z,v0.w,v1.x,v1.y,v1.z,v1.w,v2.x,v2.y};
            float rrq[4];
            #pragma unroll
            for (int p = 0; p < 4; p++) rrq[p] = qe[p] * rh[kh];
            #pragma unroll
            for (int j = 0; j < 7; j++) {
                #pragma unroll
                for (int p = 0; p < 4; p++) {
                    float l = fmaf(qe[p], kf[p + j], rrq[p]);
                    float e;
                    asm("ex2.approx.ftz.f32 %0, %1;" : "=f"(e) : "f"(l));
                    s[p] += e;
                    a[p] = fmaf(e, vf[p + j], a[p]);
                }
            }
        }
    } else {
        // rel depends on kw only: precompute qe[p]*rel_w[j]
        float rq[7][4];
        #pragma unroll
        for (int j = 0; j < 7; j++) {
            float rw = rel_w[(c - 64) * 7 + j];
            #pragma unroll
            for (int p = 0; p < 4; p++) rq[j][p] = qe[p] * rw;
        }

        #pragma unroll
        for (int kh = 0; kh < 7; kh++) {
            int base = (r + kh) * SROW + x0;
            float4 k0 = *(const float4*)&skm[base];
            float4 k1 = *(const float4*)&skm[base + 4];
            float4 k2 = *(const float4*)&skm[base + 8];
            float4 v0 = *(const float4*)&svm[base];
            float4 v1 = *(const float4*)&svm[base + 4];
            float4 v2 = *(const float4*)&svm[base + 8];
            float kf[10] = {k0.x,k0.y,k0.z,k0.w,k1.x,k1.y,k1.z,k1.w,k2.x,k2.y};
            float vf[10] = {v0.x,v0.y,v0.z,v0.w,v1.x,v1.y,v1.z,v1.w,v2.x,v2.y};
            #pragma unroll
            for (int j = 0; j < 7; j++) {
                #pragma unroll
                for (int p = 0; p < 4; p++) {
                    float l = fmaf(qe[p], kf[p + j], rq[j][p]);
                    float e;
                    asm("ex2.approx.ftz.f32 %0, %1;" : "=f"(e) : "f"(l));
                    s[p] += e;
                    a[p] = fmaf(e, vf[p + j], a[p]);
                }
            }
        }
    }

    float4 o;
    o.x = __fdividef(a[0], s[0]);
    o.y = __fdividef(a[1], s[1]);
    o.z = __fdividef(a[2], s[2]);
    o.w = __fdividef(a[3], s[3]);
    *(float4*)&out[imgoff + (size_t)(h0 + r) * 96 + w0 + x0] = o;
}

// ---------------------------------------------------------------------------
// Launch
// inputs: 0=x [2,128,96,96], 1=v [2,128,96,96], 2=w_q [128,128],
//         3=w_k [128,128], 4=rel_h [64*7], 5=rel_w [64*7]
// out: [2,128,96,96] float32
// ---------------------------------------------------------------------------
extern "C" void kernel_launch(void* const* d_in, const int* in_sizes, int n_in,
                              void* d_out, int out_size)
{
    const float* x     = (const float*)d_in[0];
    const float* v     = (const float*)d_in[1];
    const float* wq    = (const float*)d_in[2];
    const float* wk    = (const float*)d_in[3];
    const float* rel_h = (const float*)d_in[4];
    const float* rel_w = (const float*)d_in[5];
    float* out = (float*)d_out;

    qk_gemm_kernel<<<NPIX / 32, 256>>>(x, wq, wk);

    dim3 grid(18, C_, B_);   // 18 tiles of 16x32 per (b,c)
    attn_kernel<<<grid, 128>>>(v, rel_h, rel_w, out);
}